// round 9
// baseline (speedup 1.0000x reference)
#include <cuda_runtime.h>

#define BSEQ 512
#define LSEQ 512
#define AA   20
#define CCH  8
#define NREST 8
#define XPITCH 258   // xT row pitch (words): even (LDS.64 align), ==2 mod 32

// Packed f32x2 FMA: acc += a * b, two independent fp32 lanes (sm_100+).
#define FFMA2(acc, a, b) \
    asm("fma.rn.f32x2 %0, %1, %2, %0;" : "+l"(acc) : "l"(a), "l"(b))
#define UNPACK2(lo, hi, v) \
    asm("mov.b64 {%0, %1}, %2;" : "=f"(lo), "=f"(hi) : "l"(v))

#define CP_ASYNC16(smem_u32, gptr) \
    asm volatile("cp.async.cg.shared.global [%0], [%1], 16;" \
                 :: "r"(smem_u32), "l"(gptr))
#define CP_COMMIT() asm volatile("cp.async.commit_group;")
#define CP_WAIT0()  asm volatile("cp.async.wait_group 0;")

// Precomputed: effective conv map (transposed, [c][p]) and U = I + V
__device__ float g_W[CCH][LSEQ];
__device__ float g_U[AA * AA];

// ---------------------------------------------------------------------------
// Precompute kernel (proven): blocks 0..7 -> one W_eff channel via the
// adjoint of the conv+pool pipeline; block 8 -> U.
// ---------------------------------------------------------------------------
template<int LEN2>
__device__ __forceinline__ void adj_layer(const float (*cur)[256],
                                          float (*nxt)[256],
                                          const float* __restrict__ w) {
    for (int idx = threadIdx.x; idx < CCH * LEN2; idx += 256) {
        const int i = idx / LEN2;
        const int p = idx % LEN2;
        float acc = 0.f;
        #pragma unroll
        for (int o = 0; o < CCH; ++o) {
            #pragma unroll
            for (int k = 0; k < 3; ++k) {
                const int q = p - k + 1;
                if (q >= 0 && q < LEN2)
                    acc += w[(o * CCH + i) * 3 + k] * 0.5f * cur[o][q >> 1];
            }
        }
        nxt[i][p] = acc;
    }
    __syncthreads();
}

__global__ void __launch_bounds__(256)
precompute_kernel(const float* __restrict__ lpm,
                  const float* __restrict__ pm,
                  const float* __restrict__ w_first,
                  const float* __restrict__ w_rest) {
    const int blk = blockIdx.x;
    const int tid = threadIdx.x;

    if (blk < CCH) {
        __shared__ float bufA[CCH][256];
        __shared__ float bufB[CCH][256];
        __shared__ float wsh[NREST * CCH * CCH * 3];

        for (int i = tid; i < NREST * CCH * CCH * 3; i += 256)
            wsh[i] = w_rest[i];
        if (tid < CCH) bufA[tid][0] = (tid == blk) ? 1.f : 0.f;
        __syncthreads();

        float (*cur)[256] = bufA;
        float (*nxt)[256] = bufB;
        float (*tmp)[256];
        #define STEP(L2, LI) \
            adj_layer<L2>(cur, nxt, wsh + (LI) * 192); \
            tmp = cur; cur = nxt; nxt = tmp;
        STEP(2, 7)  STEP(4, 6)  STEP(8, 5)   STEP(16, 4)
        STEP(32, 3) STEP(64, 2) STEP(128, 1) STEP(256, 0)
        #undef STEP

        for (int p = tid; p < LSEQ; p += 256) {
            float acc = 0.f;
            #pragma unroll
            for (int o = 0; o < CCH; ++o) {
                #pragma unroll
                for (int k = 0; k < 3; ++k) {
                    const int q = p - k + 1;
                    if (q >= 0 && q < LSEQ)
                        acc += w_first[o * 3 + k] * 0.5f * cur[o][q >> 1];
                }
            }
            g_W[blk][p] = acc;            // transposed layout [c][p]
        }
    } else {
        // U[a][i] = delta(a,i) + V[a][i]
        for (int idx = tid; idx < AA * AA; idx += 256) {
            const int a = idx / AA, i = idx % AA;
            float v = (a == i) ? 1.f : 0.f;
            if (i != a && i != AA - 1) {
                const int r = (a < i) ? a : i;
                const int c = (a < i) ? i : a;
                float l = lpm[r * AA + c];
                l = fminf(fmaxf(l, 1e-3f), 1.f);
                v = l * pm[r * AA + c];
            }
            g_U[idx] = v;
        }
    }
}

// ---------------------------------------------------------------------------
// Main kernel: ONE BLOCK PER SEQUENCE (grid 512), two 256-position chunks,
// cp.async software pipeline: chunk(i+1) streams into smem while chunk(i)
// is transposed + GEMMed. Accumulators span K=512 -> plain stores, no atomics.
// ---------------------------------------------------------------------------
__global__ void __launch_bounds__(256, 4)
main_kernel(const float* __restrict__ x, float* __restrict__ out) {
    __shared__ __align__(16) float nat[256 * AA];   // 20480 B, natural layout
    __shared__ float xT[AA * XPITCH];               // 20640 B, [a][p] pitch 258
    __shared__ float W_sh[CCH * 256];               //  8192 B, per-chunk half
    __shared__ float g_sh[AA][CCH];

    const int b   = blockIdx.x;
    const int tid = threadIdx.x;
    const int s   = tid & 31;
    const int w   = tid >> 5;
    const int gq  = w >> 1;                 // a-group 0..3 (rows 5gq..5gq+4)
    const int h   = w & 1;                  // c-half 0..1 (cols 4h..4h+3)

    const unsigned nat_base =
        (unsigned)__cvta_generic_to_shared(nat) + (unsigned)tid * 16u;
    const char* xg = reinterpret_cast<const char*>(x) + (size_t)b * 40960;

    // Issue chunk0 cp.async (5 x 16B per thread, contiguous 20KB).
    #pragma unroll
    for (int it = 0; it < 5; ++it)
        CP_ASYNC16(nat_base + it * 4096u, xg + (tid + it * 256) * 16);
    CP_COMMIT();

    // Packed accumulators: lo = even-p partial, hi = odd-p partial (K=512).
    unsigned long long acc2[5][4];
    #pragma unroll
    for (int m = 0; m < 5; ++m)
        #pragma unroll
        for (int n = 0; n < 4; ++n) acc2[m][n] = 0ULL;

    #pragma unroll
    for (int ch = 0; ch < 2; ++ch) {
        // Stage this chunk's W half [8][256] (g_W hot in L2).
        {
            const float4* Wg = reinterpret_cast<const float4*>(g_W);
            #pragma unroll
            for (int it = 0; it < 2; ++it) {
                const int i = tid + it * 256;    // < 512
                const int c = i >> 6, p4 = i & 63;
                reinterpret_cast<float4*>(W_sh)[c * 64 + p4] =
                    Wg[c * 128 + ch * 64 + p4];
            }
        }
        CP_WAIT0();
        __syncthreads();                     // nat(ch) + W_sh visible

        // Transpose nat -> xT: 5 conflict-free LDS.128 + 20 STS (<=2-way).
        float4 tv[5];
        #pragma unroll
        for (int it = 0; it < 5; ++it)
            tv[it] = reinterpret_cast<const float4*>(nat)[tid + it * 256];
        #pragma unroll
        for (int it = 0; it < 5; ++it) {
            const int i  = tid + it * 256;
            const int p  = i / 5;
            const int a0 = (i - p * 5) * 4;
            xT[(a0 + 0) * XPITCH + p] = tv[it].x;
            xT[(a0 + 1) * XPITCH + p] = tv[it].y;
            xT[(a0 + 2) * XPITCH + p] = tv[it].z;
            xT[(a0 + 3) * XPITCH + p] = tv[it].w;
        }
        __syncthreads();                     // xT ready; nat reads done

        // Kick chunk1 fetch; its DRAM time hides under GEMM(ch=0).
        if (ch == 0) {
            #pragma unroll
            for (int it = 0; it < 5; ++it)
                CP_ASYNC16(nat_base + it * 4096u,
                           xg + 20480 + (tid + it * 256) * 16);
            CP_COMMIT();
        }

        // GEMM: lane s covers pairs {64j+2s, 64j+2s+1}; all LDS.64,
        // conflict-free on both operands (R8-proven).
        #pragma unroll
        for (int j = 0; j < 4; ++j) {
            const int off = 64 * j + 2 * s;
            unsigned long long w2[4];
            #pragma unroll
            for (int n = 0; n < 4; ++n)
                w2[n] = *reinterpret_cast<const unsigned long long*>(
                    &W_sh[(h * 4 + n) * 256 + off]);
            #pragma unroll
            for (int m = 0; m < 5; ++m) {
                const unsigned long long x2 =
                    *reinterpret_cast<const unsigned long long*>(
                        &xT[(gq * 5 + m) * XPITCH + off]);
                #pragma unroll
                for (int n = 0; n < 4; ++n)
                    FFMA2(acc2[m][n], x2, w2[n]);
            }
        }
        if (ch == 0) __syncthreads();        // GEMM0 reads done before next W/xT
    }

    // Fold even/odd halves -> scalar acc[5][4].
    float acc[5][4];
    #pragma unroll
    for (int m = 0; m < 5; ++m)
        #pragma unroll
        for (int n = 0; n < 4; ++n) {
            float lo, hi;
            UNPACK2(lo, hi, acc2[m][n]);
            acc[m][n] = lo + hi;
        }

    // Value-combining butterfly reduce over lanes.
    const bool hi16 = (s & 16) != 0;
    const bool hi8  = (s & 8) != 0;
    float r1[5][2];
    #pragma unroll
    for (int m = 0; m < 5; ++m) {
        #pragma unroll
        for (int u = 0; u < 2; ++u) {
            const float a  = acc[m][2 * u];
            const float bb = acc[m][2 * u + 1];
            const float keep = hi16 ? bb : a;
            const float send = hi16 ? a : bb;
            r1[m][u] = keep + __shfl_xor_sync(0xffffffffu, send, 16);
        }
    }
    float r2[5];
    #pragma unroll
    for (int m = 0; m < 5; ++m) {
        const float a  = r1[m][0];
        const float bb = r1[m][1];
        const float keep = hi8 ? bb : a;
        const float send = hi8 ? a : bb;
        r2[m] = keep + __shfl_xor_sync(0xffffffffu, send, 8);
    }
    #pragma unroll
    for (int m = 0; m < 5; ++m) {
        r2[m] += __shfl_xor_sync(0xffffffffu, r2[m], 4);
        r2[m] += __shfl_xor_sync(0xffffffffu, r2[m], 2);
        r2[m] += __shfl_xor_sync(0xffffffffu, r2[m], 1);
    }
    if ((s & 7) == 0) {
        const int n = 2 * ((s >> 3) & 1) + ((s >> 4) & 1);
        #pragma unroll
        for (int m = 0; m < 5; ++m)
            g_sh[gq * 5 + m][h * 4 + n] = r2[m];
    }
    __syncthreads();

    // out[b,i,c] = sum_a U[a][i] * g[a][c]   -- plain store, no atomics.
    if (tid < AA * CCH) {
        const int i = tid >> 3;
        const int c = tid & 7;
        float r = 0.f;
        #pragma unroll
        for (int a = 0; a < AA; ++a)
            r += __ldg(&g_U[a * AA + i]) * g_sh[a][c];
        out[(size_t)b * (AA * CCH) + tid] = r;
    }
}

// ---------------------------------------------------------------------------
extern "C" void kernel_launch(void* const* d_in, const int* in_sizes, int n_in,
                              void* d_out, int out_size) {
    const float* x       = (const float*)d_in[0];
    const float* lpm     = (const float*)d_in[2];
    const float* pm      = (const float*)d_in[3];
    const float* w_first = (const float*)d_in[4];
    const float* w_rest  = (const float*)d_in[5];
    float* out = (float*)d_out;

    precompute_kernel<<<CCH + 1, 256>>>(lpm, pm, w_first, w_rest);
    main_kernel<<<BSEQ, 256>>>(x, out);
}

// round 10
// speedup vs baseline: 1.2600x; 1.2600x over previous
#include <cuda_runtime.h>

#define BSEQ 512
#define LSEQ 512
#define AA   20
#define CCH  8
#define NREST 8
#define XPITCH 258   // x_shT row pitch (words): even (LDS.64 align), ==2 mod 32

// Packed f32x2 FMA: acc += a * b, two independent fp32 lanes (sm_100+).
#define FFMA2(acc, a, b) \
    asm("fma.rn.f32x2 %0, %1, %2, %0;" : "+l"(acc) : "l"(a), "l"(b))
#define UNPACK2(lo, hi, v) \
    asm("mov.b64 {%0, %1}, %2;" : "=f"(lo), "=f"(hi) : "l"(v))

// Precomputed: effective conv map (transposed, [c][p]) and U = I + V
__device__ float g_W[CCH][LSEQ];
__device__ float g_U[AA * AA];

// ---------------------------------------------------------------------------
// Precompute kernel (primary): triggers PDL at entry so the main kernel can
// start staging x immediately. Blocks 0..7 -> one W_eff channel via the
// adjoint of the conv+pool pipeline; block 8 -> U; blocks 9..168 -> zero out.
// ---------------------------------------------------------------------------
template<int LEN2>
__device__ __forceinline__ void adj_layer(const float (*cur)[256],
                                          float (*nxt)[256],
                                          const float* __restrict__ w) {
    for (int idx = threadIdx.x; idx < CCH * LEN2; idx += 256) {
        const int i = idx / LEN2;
        const int p = idx % LEN2;
        float acc = 0.f;
        #pragma unroll
        for (int o = 0; o < CCH; ++o) {
            #pragma unroll
            for (int k = 0; k < 3; ++k) {
                const int q = p - k + 1;
                if (q >= 0 && q < LEN2)
                    acc += w[(o * CCH + i) * 3 + k] * 0.5f * cur[o][q >> 1];
            }
        }
        nxt[i][p] = acc;
    }
    __syncthreads();
}

__global__ void __launch_bounds__(256)
precompute_kernel(const float* __restrict__ lpm,
                  const float* __restrict__ pm,
                  const float* __restrict__ w_first,
                  const float* __restrict__ w_rest,
                  float* __restrict__ out) {
#if __CUDA_ARCH__ >= 900
    cudaTriggerProgrammaticLaunchCompletion();   // release secondary ASAP
#endif
    const int blk = blockIdx.x;
    const int tid = threadIdx.x;

    if (blk < CCH) {
        __shared__ float bufA[CCH][256];
        __shared__ float bufB[CCH][256];
        __shared__ float wsh[NREST * CCH * CCH * 3];

        for (int i = tid; i < NREST * CCH * CCH * 3; i += 256)
            wsh[i] = w_rest[i];
        if (tid < CCH) bufA[tid][0] = (tid == blk) ? 1.f : 0.f;
        __syncthreads();

        float (*cur)[256] = bufA;
        float (*nxt)[256] = bufB;
        float (*tmp)[256];
        #define STEP(L2, LI) \
            adj_layer<L2>(cur, nxt, wsh + (LI) * 192); \
            tmp = cur; cur = nxt; nxt = tmp;
        STEP(2, 7)  STEP(4, 6)  STEP(8, 5)   STEP(16, 4)
        STEP(32, 3) STEP(64, 2) STEP(128, 1) STEP(256, 0)
        #undef STEP

        for (int p = tid; p < LSEQ; p += 256) {
            float acc = 0.f;
            #pragma unroll
            for (int o = 0; o < CCH; ++o) {
                #pragma unroll
                for (int k = 0; k < 3; ++k) {
                    const int q = p - k + 1;
                    if (q >= 0 && q < LSEQ)
                        acc += w_first[o * 3 + k] * 0.5f * cur[o][q >> 1];
                }
            }
            g_W[blk][p] = acc;            // transposed layout [c][p]
        }
    } else if (blk == CCH) {
        // U[a][i] = delta(a,i) + V[a][i]
        for (int idx = tid; idx < AA * AA; idx += 256) {
            const int a = idx / AA, i = idx % AA;
            float v = (a == i) ? 1.f : 0.f;
            if (i != a && i != AA - 1) {
                const int r = (a < i) ? a : i;
                const int c = (a < i) ? i : a;
                float l = lpm[r * AA + c];
                l = fminf(fmaxf(l, 1e-3f), 1.f);
                v = l * pm[r * AA + c];
            }
            g_U[idx] = v;
        }
    } else {
        const int z = blk - (CCH + 1);          // 0..159
        if (tid < 128)
            reinterpret_cast<float4*>(out)[z * 128 + tid] =
                make_float4(0.f, 0.f, 0.f, 0.f);
    }
}

// ---------------------------------------------------------------------------
// Main kernel (secondary, PDL): grid 1024 = 512 sequences x 2 halves.
// Stage x FIRST (independent of primary), then grid-dependency-sync, then
// stage W and run the R8 FFMA2 GEMM + value-combining reduce + U epilogue.
// ---------------------------------------------------------------------------
__global__ void __launch_bounds__(256, 4)
main_kernel(const float* __restrict__ x, float* __restrict__ out) {
    __shared__ float x_shT[AA * XPITCH];    // 20640 B, [a][p] pitch 258
    __shared__ float W_sh[CCH * 256];       //  8192 B
    __shared__ float g_sh[AA][CCH];

    const int bi   = blockIdx.x;
    const int b    = bi >> 1;
    const int half = bi & 1;
    const int tid  = threadIdx.x;
    const int s    = tid & 31;
    const int w    = tid >> 5;
    const int gq   = w >> 1;                // a-group 0..3 (rows 5gq..5gq+4)
    const int h    = w & 1;                 // c-half 0..1 (cols 4h..4h+3)

    // Stage x half-chunk FIRST: coalesced float4 global loads, transposed
    // scatter (store banks: 258*a + p == (2a + p) mod 32 -> <=2-way). This
    // overlaps with the still-running precompute kernel.
    {
        const float4* xg = reinterpret_cast<const float4*>(x)
                         + (size_t)b * 2560 + half * 1280;
        #pragma unroll
        for (int it = 0; it < 5; ++it) {
            const int i = tid + it * 256;    // < 1280
            const float4 v = xg[i];
            const int p  = i / 5;
            const int a0 = (i - p * 5) * 4;
            x_shT[(a0 + 0) * XPITCH + p] = v.x;
            x_shT[(a0 + 1) * XPITCH + p] = v.y;
            x_shT[(a0 + 2) * XPITCH + p] = v.z;
            x_shT[(a0 + 3) * XPITCH + p] = v.w;
        }
    }

    // Wait for primary grid completion (g_W, g_U, zeroed out all visible).
#if __CUDA_ARCH__ >= 900
    cudaGridDependencySynchronize();
#endif

    // Stage W chunk [8][256].
    {
        const float4* Wg = reinterpret_cast<const float4*>(g_W);
        #pragma unroll
        for (int it = 0; it < 2; ++it) {
            const int i = tid + it * 256;    // < 512
            const int c = i >> 6, p4 = i & 63;
            reinterpret_cast<float4*>(W_sh)[c * 64 + p4] =
                Wg[c * 128 + half * 64 + p4];
        }
    }
    __syncthreads();

    // Packed accumulators: lo = even-p partial, hi = odd-p partial.
    unsigned long long acc2[5][4];
    #pragma unroll
    for (int m = 0; m < 5; ++m)
        #pragma unroll
        for (int n = 0; n < 4; ++n) acc2[m][n] = 0ULL;

    // Lane s covers position pairs {64j+2s, 64j+2s+1}, j = 0..3. All LDS.64,
    // conflict-free on both operands (R8-proven).
    #pragma unroll
    for (int j = 0; j < 4; ++j) {
        const int off = 64 * j + 2 * s;
        unsigned long long w2[4];
        #pragma unroll
        for (int n = 0; n < 4; ++n)
            w2[n] = *reinterpret_cast<const unsigned long long*>(
                &W_sh[(h * 4 + n) * 256 + off]);
        #pragma unroll
        for (int m = 0; m < 5; ++m) {
            const unsigned long long x2 =
                *reinterpret_cast<const unsigned long long*>(
                    &x_shT[(gq * 5 + m) * XPITCH + off]);
            #pragma unroll
            for (int n = 0; n < 4; ++n)
                FFMA2(acc2[m][n], x2, w2[n]);
        }
    }

    // Fold even/odd halves -> scalar acc[5][4].
    float acc[5][4];
    #pragma unroll
    for (int m = 0; m < 5; ++m)
        #pragma unroll
        for (int n = 0; n < 4; ++n) {
            float lo, hi;
            UNPACK2(lo, hi, acc2[m][n]);
            acc[m][n] = lo + hi;
        }

    // Value-combining butterfly reduce over lanes.
    const bool hi16 = (s & 16) != 0;
    const bool hi8  = (s & 8) != 0;
    float r1[5][2];
    #pragma unroll
    for (int m = 0; m < 5; ++m) {
        #pragma unroll
        for (int u = 0; u < 2; ++u) {
            const float a  = acc[m][2 * u];
            const float bb = acc[m][2 * u + 1];
            const float keep = hi16 ? bb : a;
            const float send = hi16 ? a : bb;
            r1[m][u] = keep + __shfl_xor_sync(0xffffffffu, send, 16);
        }
    }
    float r2[5];
    #pragma unroll
    for (int m = 0; m < 5; ++m) {
        const float a  = r1[m][0];
        const float bb = r1[m][1];
        const float keep = hi8 ? bb : a;
        const float send = hi8 ? a : bb;
        r2[m] = keep + __shfl_xor_sync(0xffffffffu, send, 8);
    }
    #pragma unroll
    for (int m = 0; m < 5; ++m) {
        r2[m] += __shfl_xor_sync(0xffffffffu, r2[m], 4);
        r2[m] += __shfl_xor_sync(0xffffffffu, r2[m], 2);
        r2[m] += __shfl_xor_sync(0xffffffffu, r2[m], 1);
    }
    if ((s & 7) == 0) {
        const int n = 2 * ((s >> 3) & 1) + ((s >> 4) & 1);
        #pragma unroll
        for (int m = 0; m < 5; ++m)
            g_sh[gq * 5 + m][h * 4 + n] = r2[m];
    }
    __syncthreads();

    // out[b,i,c] += sum_a U[a][i] * g[a][c]   (2 halves combine via atomics)
    if (tid < AA * CCH) {
        const int i = tid >> 3;
        const int c = tid & 7;
        float r = 0.f;
        #pragma unroll
        for (int a = 0; a < AA; ++a)
            r += __ldg(&g_U[a * AA + i]) * g_sh[a][c];
        atomicAdd(&out[(size_t)b * (AA * CCH) + tid], r);
    }
}

// ---------------------------------------------------------------------------
extern "C" void kernel_launch(void* const* d_in, const int* in_sizes, int n_in,
                              void* d_out, int out_size) {
    const float* x       = (const float*)d_in[0];
    const float* lpm     = (const float*)d_in[2];
    const float* pm      = (const float*)d_in[3];
    const float* w_first = (const float*)d_in[4];
    const float* w_rest  = (const float*)d_in[5];
    float* out = (float*)d_out;

    // Primary: precompute W_eff / U and zero `out`.
    precompute_kernel<<<CCH + 1 + 160, 256>>>(lpm, pm, w_first, w_rest, out);

    // Secondary: PDL launch — may begin (stage x) while primary still runs;
    // cudaGridDependencySynchronize() inside orders the g_W/g_U/out reads.
    cudaLaunchConfig_t cfg = {};
    cfg.gridDim  = dim3(BSEQ * 2, 1, 1);
    cfg.blockDim = dim3(256, 1, 1);
    cfg.dynamicSmemBytes = 0;
    cfg.stream = 0;
    cudaLaunchAttribute attrs[1];
    attrs[0].id = cudaLaunchAttributeProgrammaticStreamSerialization;
    attrs[0].val.programmaticStreamSerializationAllowed = 1;
    cfg.attrs = attrs;
    cfg.numAttrs = 1;
    cudaLaunchKernelEx(&cfg, main_kernel, x, (float*)d_out);
}